// round 10
// baseline (speedup 1.0000x reference)
#include <cuda_runtime.h>
#include <cuda_bf16.h>

#define NMAX 100352
#define THREADS 256
#define FULL 0xffffffffu

// ---- scratch (device globals; zero-initialized at module load) ----
// g_deg_* are re-zeroed inside k_prep each launch -> deterministic.
__device__ __align__(256) int   g_deg_s[NMAX];
__device__ __align__(256) int   g_deg_d[NMAX];
__device__ __align__(256) float g_ns[NMAX];
__device__ __align__(256) float g_nd[NMAX];
__device__ __align__(256) float g_hx1[NMAX * 32];   // ns * (feat @ W1)
__device__ __align__(256) float g_agg1[NMAX * 32];  // RED accumulator (pre-nd)
__device__ __align__(256) float g_h2x[NMAX * 16];   // (relu(nd*agg+b1)*ns) @ W2

// K1: integer degree histogram (4 edges/thread)
__global__ void k_deg(const int* __restrict__ src, const int* __restrict__ dst, int e) {
    int t = blockIdx.x * blockDim.x + threadIdx.x;
    int base = t * 4;
    if (base + 3 < e) {
        int4 s4 = *(const int4*)(src + base);
        int4 d4 = *(const int4*)(dst + base);
        atomicAdd(&g_deg_s[s4.x], 1); atomicAdd(&g_deg_s[s4.y], 1);
        atomicAdd(&g_deg_s[s4.z], 1); atomicAdd(&g_deg_s[s4.w], 1);
        atomicAdd(&g_deg_d[d4.x], 1); atomicAdd(&g_deg_d[d4.y], 1);
        atomicAdd(&g_deg_d[d4.z], 1); atomicAdd(&g_deg_d[d4.w], 1);
    } else {
        for (int i = base; i < e; i++) {
            atomicAdd(&g_deg_s[src[i]], 1);
            atomicAdd(&g_deg_d[dst[i]], 1);
        }
    }
}

// K2: fused prep over grid of n*8 threads:
//  t < n*8 : zero g_agg1 (float4 lanes, coalesced)
//  t < n*4 : out[t] = b2 broadcast (float4)
//  t < n   : norms from degrees; re-zero degree tables for next launch
__global__ void k_prep(float* __restrict__ out, const float* __restrict__ b2, int n) {
    int t = blockIdx.x * blockDim.x + threadIdx.x;
    if (t < n * 8) ((float4*)g_agg1)[t] = make_float4(0.f, 0.f, 0.f, 0.f);
    if (t < n * 4) ((float4*)out)[t] = ((const float4*)b2)[t & 3];
    if (t < n) {
        g_ns[t] = rsqrtf(fmaxf((float)g_deg_s[t], 1.0f));
        g_nd[t] = rsqrtf(fmaxf((float)g_deg_d[t], 1.0f));
        g_deg_s[t] = 0;
        g_deg_d[t] = 0;
    }
}

// K3: xform1 (smem staged): g_hx1[n,:] = ns[n] * (feat[n,:] @ W1)
__global__ void __launch_bounds__(THREADS) k_xform1(const float* __restrict__ feat,
                                                    const float* __restrict__ W1, int n) {
    __shared__ float sf[256 * 33];
    int tid = threadIdx.x;
    int lane = tid & 31, w = tid >> 5;
    float w1[32];
#pragma unroll
    for (int k = 0; k < 32; k++) w1[k] = __ldg(W1 + k * 32 + lane);

    int base = blockIdx.x * 256;
    int cnt = min(256, n - base);
    for (int i = tid; i < cnt * 32; i += 256) {
        int node = i >> 5, col = i & 31;
        sf[node * 33 + col] = feat[(size_t)(base + node) * 32 + col];
    }
    __syncthreads();

    for (int t = 0; t < 32; t += 2) {
        int l0 = w * 32 + t, l1 = l0 + 1;
        if (l0 >= cnt) break;
        float acc0 = 0.f, acc1 = 0.f;
        const float* r0 = sf + l0 * 33;
        const float* r1 = sf + l1 * 33;
        bool has1 = (l1 < cnt);
#pragma unroll
        for (int k = 0; k < 32; k++) {
            acc0 = fmaf(r0[k], w1[k], acc0);
            acc1 = fmaf(r1[k], w1[k], acc1);
        }
        int n0 = base + l0;
        g_hx1[(size_t)n0 * 32 + lane] = acc0 * g_ns[n0];
        if (has1) g_hx1[(size_t)(n0 + 1) * 32 + lane] = acc1 * g_ns[n0 + 1];
    }
}

// K4: edge RED layer 1: 4 threads/edge, TWO float4 chunks per thread (c, c+4).
// Two independent gather->RED chains per thread => 2x MLP; index loads halved.
__global__ void k_edge1(const int* __restrict__ src, const int* __restrict__ dst,
                        const float* __restrict__ ew, int e) {
    int t = blockIdx.x * blockDim.x + threadIdx.x;
    if (t >= e * 4) return;
    int eid = t >> 2;
    int c = t & 3;
    int s = __ldg(src + eid);
    int d = __ldg(dst + eid);
    float w = __ldg(ew + eid);
    const float4* row = (const float4*)(g_hx1 + (size_t)s * 32);
    float4 v0 = row[c];
    float4 v1 = row[c + 4];
    v0.x *= w; v0.y *= w; v0.z *= w; v0.w *= w;
    v1.x *= w; v1.y *= w; v1.z *= w; v1.w *= w;
    float* p = g_agg1 + (size_t)d * 32;
    asm volatile("red.global.add.v4.f32 [%0], {%1,%2,%3,%4};"
                 :: "l"(p + c * 4), "f"(v0.x), "f"(v0.y), "f"(v0.z), "f"(v0.w)
                 : "memory");
    asm volatile("red.global.add.v4.f32 [%0], {%1,%2,%3,%4};"
                 :: "l"(p + (c + 4) * 4), "f"(v1.x), "f"(v1.y), "f"(v1.z), "f"(v1.w)
                 : "memory");
}

// K5: xform2 (smem staged): h = relu(nd*agg + b1) * ns; g_h2x = h @ W2
__global__ void __launch_bounds__(THREADS) k_xform2(const float* __restrict__ W2,
                                                    const float* __restrict__ b1, int n) {
    __shared__ float sf[256 * 33];
    __shared__ float sb1[32];
    int tid = threadIdx.x;
    int lane = tid & 31, w = tid >> 5;
    int p = lane >> 4, j = lane & 15;
    for (int i = tid; i < 32; i += 256) sb1[i] = __ldg(b1 + i);
    float w2[32];
#pragma unroll
    for (int k = 0; k < 32; k++) w2[k] = __ldg(W2 + k * 16 + j);
    __syncthreads();

    int base = blockIdx.x * 256;
    int cnt = min(256, n - base);
    for (int i = tid; i < cnt * 32; i += 256) {
        int node = i >> 5, col = i & 31;
        int gn = base + node;
        float a = g_agg1[(size_t)gn * 32 + col];
        sf[node * 33 + col] = fmaxf(fmaf(a, g_nd[gn], sb1[col]), 0.f) * g_ns[gn];
    }
    __syncthreads();

    for (int t = 0; t < 32; t += 2) {
        int l = w * 32 + t + p;
        if (l >= cnt) continue;
        float acc = 0.f;
        const float* r = sf + l * 33;
#pragma unroll
        for (int k = 0; k < 32; k++) acc = fmaf(r[k], w2[k], acc);
        g_h2x[(size_t)(base + l) * 16 + j] = acc;
    }
}

// K6: edge RED layer 2: 2 threads/edge, TWO float4 chunks per thread (c, c+2).
__global__ void k_edge2(const int* __restrict__ src, const int* __restrict__ dst,
                        const float* __restrict__ ew, float* __restrict__ out, int e) {
    int t = blockIdx.x * blockDim.x + threadIdx.x;
    if (t >= e * 2) return;
    int eid = t >> 1;
    int c = t & 1;
    int s = __ldg(src + eid);
    int d = __ldg(dst + eid);
    float w = __ldg(ew + eid) * g_nd[d];
    const float4* row = (const float4*)(g_h2x + (size_t)s * 16);
    float4 v0 = row[c];
    float4 v1 = row[c + 2];
    v0.x *= w; v0.y *= w; v0.z *= w; v0.w *= w;
    v1.x *= w; v1.y *= w; v1.z *= w; v1.w *= w;
    float* p = out + (size_t)d * 16;
    asm volatile("red.global.add.v4.f32 [%0], {%1,%2,%3,%4};"
                 :: "l"(p + c * 4), "f"(v0.x), "f"(v0.y), "f"(v0.z), "f"(v0.w)
                 : "memory");
    asm volatile("red.global.add.v4.f32 [%0], {%1,%2,%3,%4};"
                 :: "l"(p + (c + 2) * 4), "f"(v1.x), "f"(v1.y), "f"(v1.z), "f"(v1.w)
                 : "memory");
}

static inline int cdiv(long long a, int b) { return (int)((a + b - 1) / b); }

extern "C" void kernel_launch(void* const* d_in, const int* in_sizes, int n_in,
                              void* d_out, int out_size) {
    const float* feat = (const float*)d_in[0];
    const int*   src  = (const int*)d_in[1];
    const int*   dst  = (const int*)d_in[2];
    const float* ew   = (const float*)d_in[3];
    const float* W1   = (const float*)d_in[4];
    const float* b1   = (const float*)d_in[5];
    const float* W2   = (const float*)d_in[6];
    const float* b2   = (const float*)d_in[7];
    float* out = (float*)d_out;

    int n = in_sizes[0] / 32;
    int e = in_sizes[1];

    k_deg   <<<cdiv(cdiv(e, 4), THREADS), THREADS>>>(src, dst, e);
    k_prep  <<<cdiv((long long)n * 8, THREADS), THREADS>>>(out, b2, n);
    k_xform1<<<cdiv(n, 256), THREADS>>>(feat, W1, n);
    k_edge1 <<<cdiv((long long)e * 4, THREADS), THREADS>>>(src, dst, ew, e);
    k_xform2<<<cdiv(n, 256), THREADS>>>(W2, b1, n);
    k_edge2 <<<cdiv((long long)e * 2, THREADS), THREADS>>>(src, dst, ew, out, e);
}

// round 11
// speedup vs baseline: 1.1434x; 1.1434x over previous
#include <cuda_runtime.h>
#include <cuda_bf16.h>

#define NMAX 100352
#define THREADS 256
#define FULL 0xffffffffu

// ---- scratch (device globals; zero-initialized at module load) ----
// g_deg_* are re-zeroed inside k_prep each launch -> deterministic.
__device__ __align__(256) int   g_deg_s[NMAX];
__device__ __align__(256) int   g_deg_d[NMAX];
__device__ __align__(256) float g_ns[NMAX];
__device__ __align__(256) float g_nd[NMAX];
__device__ __align__(256) float g_hx1[NMAX * 32];   // ns * (feat @ W1)
__device__ __align__(256) float g_agg1[NMAX * 32];  // RED accumulator (pre-nd)
__device__ __align__(256) float g_h2x[NMAX * 16];   // (relu(nd*agg+b1)*ns) @ W2

// K1: integer degree histogram (4 edges/thread)
__global__ void k_deg(const int* __restrict__ src, const int* __restrict__ dst, int e) {
    int t = blockIdx.x * blockDim.x + threadIdx.x;
    int base = t * 4;
    if (base + 3 < e) {
        int4 s4 = *(const int4*)(src + base);
        int4 d4 = *(const int4*)(dst + base);
        atomicAdd(&g_deg_s[s4.x], 1); atomicAdd(&g_deg_s[s4.y], 1);
        atomicAdd(&g_deg_s[s4.z], 1); atomicAdd(&g_deg_s[s4.w], 1);
        atomicAdd(&g_deg_d[d4.x], 1); atomicAdd(&g_deg_d[d4.y], 1);
        atomicAdd(&g_deg_d[d4.z], 1); atomicAdd(&g_deg_d[d4.w], 1);
    } else {
        for (int i = base; i < e; i++) {
            atomicAdd(&g_deg_s[src[i]], 1);
            atomicAdd(&g_deg_d[dst[i]], 1);
        }
    }
}

// K2: fused prep: zero agg1, out := b2, norms, re-zero degree tables
__global__ void k_prep(float* __restrict__ out, const float* __restrict__ b2, int n) {
    int t = blockIdx.x * blockDim.x + threadIdx.x;
    if (t < n * 8) ((float4*)g_agg1)[t] = make_float4(0.f, 0.f, 0.f, 0.f);
    if (t < n * 4) ((float4*)out)[t] = ((const float4*)b2)[t & 3];
    if (t < n) {
        g_ns[t] = rsqrtf(fmaxf((float)g_deg_s[t], 1.0f));
        g_nd[t] = rsqrtf(fmaxf((float)g_deg_d[t], 1.0f));
        g_deg_s[t] = 0;
        g_deg_d[t] = 0;
    }
}

// K3: xform1 (smem staged): g_hx1[n,:] = ns[n] * (feat[n,:] @ W1)
__global__ void __launch_bounds__(THREADS) k_xform1(const float* __restrict__ feat,
                                                    const float* __restrict__ W1, int n) {
    __shared__ float sf[256 * 33];
    int tid = threadIdx.x;
    int lane = tid & 31, w = tid >> 5;
    float w1[32];
#pragma unroll
    for (int k = 0; k < 32; k++) w1[k] = __ldg(W1 + k * 32 + lane);

    int base = blockIdx.x * 256;
    int cnt = min(256, n - base);
    for (int i = tid; i < cnt * 32; i += 256) {
        int node = i >> 5, col = i & 31;
        sf[node * 33 + col] = feat[(size_t)(base + node) * 32 + col];
    }
    __syncthreads();

    for (int t = 0; t < 32; t += 2) {
        int l0 = w * 32 + t, l1 = l0 + 1;
        if (l0 >= cnt) break;
        float acc0 = 0.f, acc1 = 0.f;
        const float* r0 = sf + l0 * 33;
        const float* r1 = sf + l1 * 33;
        bool has1 = (l1 < cnt);
#pragma unroll
        for (int k = 0; k < 32; k++) {
            acc0 = fmaf(r0[k], w1[k], acc0);
            acc1 = fmaf(r1[k], w1[k], acc1);
        }
        int n0 = base + l0;
        g_hx1[(size_t)n0 * 32 + lane] = acc0 * g_ns[n0];
        if (has1) g_hx1[(size_t)(n0 + 1) * 32 + lane] = acc1 * g_ns[n0 + 1];
    }
}

// K4: edge RED layer 1: 8 lanes/edge, one float4/lane, TWO edges per thread
// (eid and eid+half) -> 2 independent gather->RED chains, same wavefronts/edge.
__global__ void k_edge1(const int* __restrict__ src, const int* __restrict__ dst,
                        const float* __restrict__ ew, int e, int half) {
    int t = blockIdx.x * blockDim.x + threadIdx.x;
    if (t >= half * 8) return;
    int c = t & 7;
    int e0 = t >> 3;
    int e1 = e0 + half;
    bool has1 = (e1 < e);

    int s0 = __ldg(src + e0);
    int d0 = __ldg(dst + e0);
    float w0 = __ldg(ew + e0);
    int s1 = 0, d1 = 0; float w1 = 0.f;
    if (has1) {
        s1 = __ldg(src + e1);
        d1 = __ldg(dst + e1);
        w1 = __ldg(ew + e1);
    }

    float4 v0 = *(const float4*)(g_hx1 + (size_t)s0 * 32 + c * 4);
    float4 v1 = has1 ? *(const float4*)(g_hx1 + (size_t)s1 * 32 + c * 4)
                     : make_float4(0.f, 0.f, 0.f, 0.f);
    v0.x *= w0; v0.y *= w0; v0.z *= w0; v0.w *= w0;
    v1.x *= w1; v1.y *= w1; v1.z *= w1; v1.w *= w1;

    asm volatile("red.global.add.v4.f32 [%0], {%1,%2,%3,%4};"
                 :: "l"(g_agg1 + (size_t)d0 * 32 + c * 4),
                    "f"(v0.x), "f"(v0.y), "f"(v0.z), "f"(v0.w) : "memory");
    if (has1)
        asm volatile("red.global.add.v4.f32 [%0], {%1,%2,%3,%4};"
                     :: "l"(g_agg1 + (size_t)d1 * 32 + c * 4),
                        "f"(v1.x), "f"(v1.y), "f"(v1.z), "f"(v1.w) : "memory");
}

// K5: xform2 (smem staged): h = relu(nd*agg + b1) * ns; g_h2x = h @ W2
__global__ void __launch_bounds__(THREADS) k_xform2(const float* __restrict__ W2,
                                                    const float* __restrict__ b1, int n) {
    __shared__ float sf[256 * 33];
    __shared__ float sb1[32];
    int tid = threadIdx.x;
    int lane = tid & 31, w = tid >> 5;
    int p = lane >> 4, j = lane & 15;
    for (int i = tid; i < 32; i += 256) sb1[i] = __ldg(b1 + i);
    float w2[32];
#pragma unroll
    for (int k = 0; k < 32; k++) w2[k] = __ldg(W2 + k * 16 + j);
    __syncthreads();

    int base = blockIdx.x * 256;
    int cnt = min(256, n - base);
    for (int i = tid; i < cnt * 32; i += 256) {
        int node = i >> 5, col = i & 31;
        int gn = base + node;
        float a = g_agg1[(size_t)gn * 32 + col];
        sf[node * 33 + col] = fmaxf(fmaf(a, g_nd[gn], sb1[col]), 0.f) * g_ns[gn];
    }
    __syncthreads();

    for (int t = 0; t < 32; t += 2) {
        int l = w * 32 + t + p;
        if (l >= cnt) continue;
        float acc = 0.f;
        const float* r = sf + l * 33;
#pragma unroll
        for (int k = 0; k < 32; k++) acc = fmaf(r[k], w2[k], acc);
        g_h2x[(size_t)(base + l) * 16 + j] = acc;
    }
}

// K6: edge RED layer 2: 4 lanes/edge, one float4/lane, TWO edges per thread.
// nd[d] folded into weight; out pre-inited to b2.
__global__ void k_edge2(const int* __restrict__ src, const int* __restrict__ dst,
                        const float* __restrict__ ew, float* __restrict__ out,
                        int e, int half) {
    int t = blockIdx.x * blockDim.x + threadIdx.x;
    if (t >= half * 4) return;
    int c = t & 3;
    int e0 = t >> 2;
    int e1 = e0 + half;
    bool has1 = (e1 < e);

    int s0 = __ldg(src + e0);
    int d0 = __ldg(dst + e0);
    float w0 = __ldg(ew + e0);
    int s1 = 0, d1 = 0; float w1 = 0.f;
    if (has1) {
        s1 = __ldg(src + e1);
        d1 = __ldg(dst + e1);
        w1 = __ldg(ew + e1);
    }
    w0 *= g_nd[d0];
    if (has1) w1 *= g_nd[d1];

    float4 v0 = *(const float4*)(g_h2x + (size_t)s0 * 16 + c * 4);
    float4 v1 = has1 ? *(const float4*)(g_h2x + (size_t)s1 * 16 + c * 4)
                     : make_float4(0.f, 0.f, 0.f, 0.f);
    v0.x *= w0; v0.y *= w0; v0.z *= w0; v0.w *= w0;
    v1.x *= w1; v1.y *= w1; v1.z *= w1; v1.w *= w1;

    asm volatile("red.global.add.v4.f32 [%0], {%1,%2,%3,%4};"
                 :: "l"(out + (size_t)d0 * 16 + c * 4),
                    "f"(v0.x), "f"(v0.y), "f"(v0.z), "f"(v0.w) : "memory");
    if (has1)
        asm volatile("red.global.add.v4.f32 [%0], {%1,%2,%3,%4};"
                     :: "l"(out + (size_t)d1 * 16 + c * 4),
                        "f"(v1.x), "f"(v1.y), "f"(v1.z), "f"(v1.w) : "memory");
}

static inline int cdiv(long long a, int b) { return (int)((a + b - 1) / b); }

extern "C" void kernel_launch(void* const* d_in, const int* in_sizes, int n_in,
                              void* d_out, int out_size) {
    const float* feat = (const float*)d_in[0];
    const int*   src  = (const int*)d_in[1];
    const int*   dst  = (const int*)d_in[2];
    const float* ew   = (const float*)d_in[3];
    const float* W1   = (const float*)d_in[4];
    const float* b1   = (const float*)d_in[5];
    const float* W2   = (const float*)d_in[6];
    const float* b2   = (const float*)d_in[7];
    float* out = (float*)d_out;

    int n = in_sizes[0] / 32;
    int e = in_sizes[1];
    int half = (e + 1) / 2;

    k_deg   <<<cdiv(cdiv(e, 4), THREADS), THREADS>>>(src, dst, e);
    k_prep  <<<cdiv((long long)n * 8, THREADS), THREADS>>>(out, b2, n);
    k_xform1<<<cdiv(n, 256), THREADS>>>(feat, W1, n);
    k_edge1 <<<cdiv((long long)half * 8, THREADS), THREADS>>>(src, dst, ew, e, half);
    k_xform2<<<cdiv(n, 256), THREADS>>>(W2, b1, n);
    k_edge2 <<<cdiv((long long)half * 4, THREADS), THREADS>>>(src, dst, ew, out, e, half);
}